// round 11
// baseline (speedup 1.0000x reference)
#include <cuda_runtime.h>
#include <cstdint>

// ---------------- problem constants ----------------
#define B_     4096
#define OBS_   64
#define EP_    10
#define IN_    640      // OBS*EP
#define H_     1024
#define AD_    16
#define DP_    10
#define OUT_   160      // AD*DP
#define T_     8
#define M_     (B_ * T_)   // 32768 batched rows, ordered m = b*8 + t

#define CDECAY 0.5f
#define VTH    0.5f
#define THV   (-0.172f)
#define THU    0.529f
#define THR    0.021f
#define THS    0.132f

// ---------------- device scratch ----------------
__device__ __align__(128) int8_t g_spikes[(size_t)M_ * (size_t)IN_];   // 21 MB, [b*8+t][i]
__device__ __align__(128) int8_t g_sa[(size_t)M_ * (size_t)H_];        // 33.5 MB
__device__ __align__(128) int8_t g_sb[(size_t)M_ * (size_t)H_];        // 33.5 MB
__device__ __align__(128) float g_x3[(size_t)M_ * (size_t)OUT_];       // 21 MB
__device__ __align__(128) float g_w1t[(size_t)IN_ * (size_t)H_];   // [640][1024]
__device__ __align__(128) float g_w2t[(size_t)H_ * (size_t)H_];    // [1024][1024]
__device__ __align__(128) float g_wot[(size_t)H_ * 256];           // [1024][256], cols>=160 zero

// ---------------- helpers ----------------
__device__ __forceinline__ uint32_t smem_u32(const void* p) {
    uint32_t a;
    asm("{ .reg .u64 t; cvta.to.shared.u64 t, %1; cvt.u32.u64 %0, t; }" : "=r"(a) : "l"(p));
    return a;
}
__device__ __forceinline__ void cp_async16(uint32_t saddr, const void* g) {
    asm volatile("cp.async.cg.shared.global [%0], [%1], 16;" :: "r"(saddr), "l"(g));
}
#define CP_COMMIT() asm volatile("cp.async.commit_group;" ::: "memory")
#define CP_WAIT0()  asm volatile("cp.async.wait_group 0;" ::: "memory")

__device__ __forceinline__ void lds_v2u64(unsigned long long& a, unsigned long long& b, uint32_t addr) {
    asm volatile("ld.shared.v2.u64 {%0,%1}, [%2];" : "=l"(a), "=l"(b) : "r"(addr));
}
__device__ __forceinline__ void sts64(uint32_t addr, unsigned long long d) {
    asm volatile("st.shared.b64 [%0], %1;" :: "r"(addr), "l"(d));
}
__device__ __forceinline__ unsigned long long dupbit(uint32_t word, int b) {
    uint32_t f = ((word >> (8 * b)) & 1u) * 0x3f800000u;
    unsigned long long d;
    asm("mov.b64 %0, {%1,%1};" : "=l"(d) : "r"(f));
    return d;
}
// packed fp32 pair FMA: per-lane IEEE RN fp32 fma (bitwise == scalar FFMA chain)
__device__ __forceinline__ void fma2(unsigned long long& d, unsigned long long a, unsigned long long b) {
    asm("fma.rn.f32x2 %0, %1, %2, %0;" : "+l"(d) : "l"(a), "l"(b));
}
__device__ __forceinline__ float f2lo(unsigned long long u) {
    return __int_as_float((int)(unsigned)(u & 0xffffffffull));
}
__device__ __forceinline__ float f2hi(unsigned long long u) {
    return __int_as_float((int)(unsigned)(u >> 32));
}

// ---------------- batched f32x2 GEMM, sequential-k fp32 semantics ----------------
// X[m][n] = sum_{k ascending} A[m][k]*W[n][k], fp32 RN FMA chain per output.
// A: s8 spikes [M][KBASE], m = b*8+t. WT: fp32 [KBASE][WLD] k-major.
// CTA 128x128, BK=32, 256 threads; thread: 8 rows (= t 0..7 of one b) x 8 cols.
// Smem: A as DUPLICATED f32x2 pairs [2][32][128] f64 (bit-expanded in staging);
//       W plain [2][32][128] f32 via cp.async. Inner k: 6 LDS + 32 fma2.
// MODE 0: plain store to X. MODE 1: fused hidden-neuron scan over t, write s8 spikes.
template<int KBASE, int MODE>
__global__ __launch_bounds__(256, 2) void gemm_f2(
    const int8_t* __restrict__ A, const float* __restrict__ WT,
    const float* __restrict__ bias,
    float* __restrict__ X, int8_t* __restrict__ S,
    int WLD, int XLD, int NTOT) {

    constexpr int KT = KBASE / 32;
    constexpr uint32_t ABUF = 32 * 128 * 8;   // dup f64
    constexpr uint32_t WBUF = 32 * 128 * 4;

    extern __shared__ char smraw[];
    const uint32_t ab0 = smem_u32(smraw);
    const uint32_t wb0 = ab0 + 2 * ABUF;

    const int tid  = threadIdx.x;
    const int trow = tid >> 4;     // 0..15
    const int tcol = tid & 15;     // 0..15
    const int bm0 = blockIdx.y * 128;
    const int bn0 = blockIdx.x * 128;

    const int arowi = tid & 127;
    const int khalf = tid >> 7;    // 0/1
    const int8_t* arow = A + (size_t)(bm0 + arowi) * KBASE + khalf * 16;

    uint4 arg;
    auto ldgA = [&](int t) { arg = *(const uint4*)(arow + t * 32); };
    auto cpW = [&](int t) {
        const float* src = WT + (size_t)(t * 32) * WLD + bn0;
        const uint32_t dst = wb0 + (uint32_t)(t & 1) * WBUF;
#pragma unroll
        for (int q = 0; q < 4; q++) {
            int ch = tid + q * 256;           // 0..1023
            int row = ch >> 5, c16 = ch & 31; // 32 rows x 32 16B-chunks
            cp_async16(dst + (uint32_t)(row * 128 + c16 * 4) * 4,
                       src + (size_t)row * WLD + c16 * 4);
        }
        CP_COMMIT();
    };
    auto stsA = [&](int t) {
        // k = khalf*16 + w*4 + b; addr = (k*128 + arowi)*8
        uint32_t base = ab0 + (uint32_t)(t & 1) * ABUF
                      + (uint32_t)(khalf * 16 * 128 + arowi) * 8u;
#pragma unroll
        for (int w = 0; w < 4; w++) {
            uint32_t x = ((const uint32_t*)&arg)[w];
#pragma unroll
            for (int b = 0; b < 4; b++)
                sts64(base + (uint32_t)((w * 4 + b) * 128) * 8u, dupbit(x, b));
        }
    };

    unsigned long long acc[8][4];
#pragma unroll
    for (int i = 0; i < 8; i++)
#pragma unroll
        for (int j = 0; j < 4; j++) acc[i][j] = 0ull;

    // prologue
    ldgA(0); cpW(0); stsA(0);

    for (int i = 0; i < KT; i++) {
        CP_WAIT0();
        __syncthreads();
        if (i + 1 < KT) { cpW(i + 1); ldgA(i + 1); }

        const uint32_t ab = ab0 + (uint32_t)(i & 1) * ABUF + (uint32_t)(trow * 8) * 8u;
        const uint32_t wb = wb0 + (uint32_t)(i & 1) * WBUF + (uint32_t)(tcol * 8) * 4u;
#pragma unroll
        for (int k = 0; k < 32; k++) {
            unsigned long long aa[8], ww[4];
            const uint32_t ak = ab + (uint32_t)(k * 128) * 8u;
            lds_v2u64(aa[0], aa[1], ak);
            lds_v2u64(aa[2], aa[3], ak + 16u);
            lds_v2u64(aa[4], aa[5], ak + 32u);
            lds_v2u64(aa[6], aa[7], ak + 48u);
            const uint32_t wk = wb + (uint32_t)(k * 128) * 4u;
            lds_v2u64(ww[0], ww[1], wk);
            lds_v2u64(ww[2], ww[3], wk + 16u);
#pragma unroll
            for (int ii = 0; ii < 8; ii++)
#pragma unroll
                for (int jj = 0; jj < 4; jj++) fma2(acc[ii][jj], aa[ii], ww[jj]);
        }
        if (i + 1 < KT) stsA(i + 1);
    }

    if (MODE == 1) {
        // fused hidden-neuron scan over t (thread rows = t 0..7 of batch b)
        float bj[8];
#pragma unroll
        for (int cc = 0; cc < 8; cc++) bj[cc] = bias[bn0 + tcol * 8 + cc];
        unsigned long long srow[8];
#pragma unroll
        for (int i = 0; i < 8; i++) srow[i] = 0ull;
#pragma unroll
        for (int j = 0; j < 4; j++) {
#pragma unroll
            for (int e = 0; e < 2; e++) {
                const int cc = 2 * j + e;
                float c = 0.0f, vv = 0.0f, rr = 0.0f, ss = 0.0f;
#pragma unroll
                for (int i = 0; i < 8; i++) {
                    float xv = e ? f2hi(acc[i][j]) : f2lo(acc[i][j]);
                    c  = c * CDECAY + xv + bj[cc];
                    vv = vv * (1.0f - ss) + ss * THR;
                    rr = rr + ss * THS;
                    float vd = vv * vv - vv - rr + c;
                    float rd = THV * vv - THU * rr;
                    vv += vd; rr += rd;
                    ss = vv > VTH ? 1.0f : 0.0f;
                    srow[i] |= (unsigned long long)(ss != 0.0f ? 1u : 0u) << (8 * cc);
                }
            }
        }
#pragma unroll
        for (int i = 0; i < 8; i++) {
            size_t row = (size_t)(bm0 + trow * 8 + i);
            *(unsigned long long*)&S[row * H_ + bn0 + tcol * 8] = srow[i];
        }
    } else {
#pragma unroll
        for (int i = 0; i < 8; i++) {
            int row = bm0 + trow * 8 + i;
#pragma unroll
            for (int j = 0; j < 4; j++) {
                int col = bn0 + tcol * 8 + 2 * j;
                if (col < NTOT) {
                    *(float2*)&X[(size_t)row * XLD + col] =
                        make_float2(f2lo(acc[i][j]), f2hi(acc[i][j]));
                }
            }
        }
    }
}

// ---------------- weight transpose: w[N][K] -> wt[K][NP], zero-pad n>=N ----------------
__global__ void transpose_w(const float* __restrict__ w, float* __restrict__ wt,
                            int N, int K, int NP) {
    __shared__ float t[32][33];
    int tx = threadIdx.x, ty = threadIdx.y;  // 32 x 8
    int bx = blockIdx.x, by = blockIdx.y;
#pragma unroll
    for (int j = 0; j < 4; j++) {
        int n = bx * 32 + ty + j * 8;
        int k = by * 32 + tx;
        t[ty + j * 8][tx] = (n < N) ? w[(size_t)n * K + k] : 0.0f;
    }
    __syncthreads();
#pragma unroll
    for (int j = 0; j < 4; j++) {
        int k = by * 32 + ty + j * 8;
        int n = bx * 32 + tx;
        wt[(size_t)k * NP + n] = t[tx][ty + j * 8];
    }
}

// ---------------- encoder (writes spikes in m = b*8+t order) ----------------
__global__ void encoder_kernel(const float* __restrict__ obs,
                               const float* __restrict__ mean,
                               const float* __restrict__ stdv) {
    int idx = blockIdx.x * blockDim.x + threadIdx.x;
    if (idx >= B_ * IN_) return;
    int b = idx / IN_;
    int i = idx - b * IN_;
    int o = i / EP_;
    float d  = obs[b * OBS_ + o] - mean[i];
    float sd = stdv[i];
    float a  = expf(-0.5f * d * d / (sd * sd));
    float volt = 0.0f;
    int8_t* sp = g_spikes + (size_t)b * T_ * IN_ + i;
#pragma unroll
    for (int t = 0; t < T_; t++) {
        volt += a;
        float s = volt > 1.0f ? 1.0f : 0.0f;
        volt -= s;
        sp[(size_t)t * IN_] = (int8_t)s;
    }
}

// ---------------- output-layer scan: lateral conv + neuron + fr + decode ----------------
__global__ __launch_bounds__(256) void scan_out(
    const float* __restrict__ x3, const float* __restrict__ b_out,
    const float* __restrict__ conn_w, const float* __restrict__ conn_b,
    const float* __restrict__ dec_w, const float* __restrict__ dec_b,
    float* __restrict__ out) {
    __shared__ float cw[AD_ * DP_ * DP_];   // 1600
    for (int i = threadIdx.x; i < AD_ * DP_ * DP_; i += blockDim.x) cw[i] = conn_w[i];
    __syncthreads();

    int idx = blockIdx.x * blockDim.x + threadIdx.x;   // (b, a)
    if (idx >= B_ * AD_) return;
    int b = idx >> 4;
    int a = idx & 15;

    float cb[DP_], bo[DP_];
#pragma unroll
    for (int j = 0; j < DP_; j++) {
        cb[j] = conn_b[a * DP_ + j];
        bo[j] = b_out[a * DP_ + j];
    }
    const float* cwa = cw + a * DP_ * DP_;

    float cur[DP_], vv[DP_], rr[DP_], sp[DP_], fr[DP_];
#pragma unroll
    for (int j = 0; j < DP_; j++) { cur[j] = 0.f; vv[j] = 0.f; rr[j] = 0.f; sp[j] = 0.f; fr[j] = 0.f; }

    for (int t = 0; t < T_; t++) {
        const float* xp = x3 + ((size_t)b * T_ + t) * OUT_ + a * DP_;
        float sn[DP_];
#pragma unroll
        for (int j = 0; j < DP_; j++) {
            float lat = cb[j];
#pragma unroll
            for (int k = 0; k < DP_; k++) lat += sp[k] * cwa[j * DP_ + k];
            float c  = cur[j] * CDECAY + xp[j] + bo[j] + lat;
            float v2 = vv[j] * (1.0f - sp[j]) + sp[j] * THR;
            float r2 = rr[j] + sp[j] * THS;
            float vd = v2 * v2 - v2 - r2 + c;
            float rd = THV * v2 - THU * r2;
            v2 += vd; r2 += rd;
            sn[j] = v2 > VTH ? 1.0f : 0.0f;
            cur[j] = c; vv[j] = v2; rr[j] = r2;
        }
#pragma unroll
        for (int j = 0; j < DP_; j++) { sp[j] = sn[j]; fr[j] += sn[j]; }
    }

    float raw = dec_b[a];
#pragma unroll
    for (int p = 0; p < DP_; p++) raw += (fr[p] * 0.125f) * dec_w[a * DP_ + p];
    out[idx] = tanhf(raw);
}

// ---------------- launch ----------------
extern "C" void kernel_launch(void* const* d_in, const int* in_sizes, int n_in,
                              void* d_out, int out_size) {
    const float* obs    = (const float*)d_in[0];
    const float* mean   = (const float*)d_in[1];
    const float* stdv   = (const float*)d_in[2];
    const float* w1     = (const float*)d_in[3];
    const float* b1     = (const float*)d_in[4];
    const float* w2     = (const float*)d_in[5];
    const float* b2     = (const float*)d_in[6];
    const float* w_out  = (const float*)d_in[7];
    const float* b_out  = (const float*)d_in[8];
    const float* conn_w = (const float*)d_in[9];
    const float* conn_b = (const float*)d_in[10];
    const float* dec_w  = (const float*)d_in[11];
    const float* dec_b  = (const float*)d_in[12];
    float* out = (float*)d_out;

    int8_t *spikes, *sa, *sb;
    float *x3, *w1t, *w2t, *wot;
    cudaGetSymbolAddress((void**)&spikes, g_spikes);
    cudaGetSymbolAddress((void**)&sa,  g_sa);
    cudaGetSymbolAddress((void**)&sb,  g_sb);
    cudaGetSymbolAddress((void**)&x3,  g_x3);
    cudaGetSymbolAddress((void**)&w1t, g_w1t);
    cudaGetSymbolAddress((void**)&w2t, g_w2t);
    cudaGetSymbolAddress((void**)&wot, g_wot);

    const int smemG = 2 * 32 * 128 * 8 + 2 * 32 * 128 * 4;  // 98304
    cudaFuncSetAttribute(gemm_f2<640, 1>,  cudaFuncAttributeMaxDynamicSharedMemorySize, smemG);
    cudaFuncSetAttribute(gemm_f2<1024, 1>, cudaFuncAttributeMaxDynamicSharedMemorySize, smemG);
    cudaFuncSetAttribute(gemm_f2<1024, 0>, cudaFuncAttributeMaxDynamicSharedMemorySize, smemG);

    {
        dim3 tb(32, 8);
        transpose_w<<<dim3(32, 20), tb>>>(w1, w1t, H_, IN_, H_);
        transpose_w<<<dim3(32, 32), tb>>>(w2, w2t, H_, H_, H_);
        transpose_w<<<dim3(8, 32),  tb>>>(w_out, wot, OUT_, H_, 256);
    }
    encoder_kernel<<<(B_ * IN_ + 255) / 256, 256>>>(obs, mean, stdv);

    // L1: s1 = scan(spikes_all @ W1)   (M=32768, K=640, N=1024, fused scan)
    gemm_f2<640, 1><<<dim3(8, M_ / 128), 256, smemG>>>(
        spikes, w1t, b1, nullptr, sa, H_, H_, H_);

    // L2: s2 = scan(s1_all @ W2)       (M=32768, K=1024, N=1024, fused scan)
    gemm_f2<1024, 1><<<dim3(8, M_ / 128), 256, smemG>>>(
        sa, w2t, b2, nullptr, sb, H_, H_, H_);

    // L3: X3 = s2_all @ Wout           (M=32768, K=1024, N=160 padded 256)
    gemm_f2<1024, 0><<<dim3(2, M_ / 128), 256, smemG>>>(
        sb, wot, nullptr, x3, nullptr, 256, OUT_, OUT_);

    // output scan: lateral + neuron + fr + decode
    scan_out<<<(B_ * AD_ + 255) / 256, 256>>>(x3, b_out, conn_w, conn_b, dec_w, dec_b, out);
}

// round 12
// speedup vs baseline: 1.1711x; 1.1711x over previous
#include <cuda_runtime.h>
#include <cstdint>

// ---------------- problem constants ----------------
#define B_     4096
#define OBS_   64
#define EP_    10
#define IN_    640      // OBS*EP
#define H_     1024
#define AD_    16
#define DP_    10
#define OUT_   160      // AD*DP
#define T_     8
#define M_     (B_ * T_)   // 32768 batched rows, ordered m = b*8 + t

#define CDECAY 0.5f
#define VTH    0.5f
#define THV   (-0.172f)
#define THU    0.529f
#define THR    0.021f
#define THS    0.132f

// ---------------- device scratch ----------------
__device__ __align__(128) int8_t g_spikes[(size_t)M_ * (size_t)IN_];   // 21 MB, [b*8+t][i]
__device__ __align__(128) int8_t g_sa[(size_t)M_ * (size_t)H_];        // 33.5 MB
__device__ __align__(128) int8_t g_sb[(size_t)M_ * (size_t)H_];        // 33.5 MB
__device__ __align__(128) float g_x3[(size_t)M_ * (size_t)OUT_];       // 21 MB
__device__ __align__(128) float g_w1t[(size_t)IN_ * (size_t)H_];   // [640][1024]
__device__ __align__(128) float g_w2t[(size_t)H_ * (size_t)H_];    // [1024][1024]
__device__ __align__(128) float g_wot[(size_t)H_ * 256];           // [1024][256], cols>=160 zero

// ---------------- helpers ----------------
__device__ __forceinline__ uint32_t smem_u32(const void* p) {
    uint32_t a;
    asm("{ .reg .u64 t; cvta.to.shared.u64 t, %1; cvt.u32.u64 %0, t; }" : "=r"(a) : "l"(p));
    return a;
}
__device__ __forceinline__ void cp_async16(uint32_t saddr, const void* g) {
    asm volatile("cp.async.cg.shared.global [%0], [%1], 16;" :: "r"(saddr), "l"(g));
}
#define CP_COMMIT() asm volatile("cp.async.commit_group;" ::: "memory")
#define CP_WAIT0()  asm volatile("cp.async.wait_group 0;" ::: "memory")

__device__ __forceinline__ void lds_v2u64(unsigned long long& a, unsigned long long& b, uint32_t addr) {
    asm volatile("ld.shared.v2.u64 {%0,%1}, [%2];" : "=l"(a), "=l"(b) : "r"(addr));
}
__device__ __forceinline__ void lds_f4(float4& v, uint32_t addr) {
    asm volatile("ld.shared.v4.f32 {%0,%1,%2,%3}, [%4];"
        : "=f"(v.x), "=f"(v.y), "=f"(v.z), "=f"(v.w) : "r"(addr));
}
__device__ __forceinline__ void sts32(uint32_t addr, uint32_t d) {
    asm volatile("st.shared.b32 [%0], %1;" :: "r"(addr), "r"(d));
}
__device__ __forceinline__ unsigned long long dup2(float x) {
    unsigned long long d;
    uint32_t u = __float_as_uint(x);
    asm("mov.b64 %0, {%1,%1};" : "=l"(d) : "r"(u));
    return d;
}
// packed fp32 pair FMA: per-lane IEEE RN fp32 fma (bitwise == scalar FFMA chain)
__device__ __forceinline__ void fma2(unsigned long long& d, unsigned long long a, unsigned long long b) {
    asm("fma.rn.f32x2 %0, %1, %2, %0;" : "+l"(d) : "l"(a), "l"(b));
}
__device__ __forceinline__ float f2lo(unsigned long long u) {
    return __int_as_float((int)(unsigned)(u & 0xffffffffull));
}
__device__ __forceinline__ float f2hi(unsigned long long u) {
    return __int_as_float((int)(unsigned)(u >> 32));
}

// ---------------- batched f32x2 GEMM, sequential-k fp32 semantics ----------------
// X[m][n] = sum_{k ascending} A[m][k]*W[n][k], fp32 RN FMA chain per output.
// A: s8 spikes [M][KBASE], m = b*8+t. WT: fp32 [KBASE][WLD] k-major.
// CTA 128x128, BK=32, 256 threads; thread: 8 rows (= t 0..7 of one b) x 8 cols.
// Smem (R10-proven): A plain f32 [2][32][128] (bit-expanded); W [2][32][128] cp.async.
// MODE 0: plain store to X. MODE 1: fused hidden-neuron scan over t, write s8 spikes.
template<int KBASE, int MODE>
__global__ __launch_bounds__(256, 2) void gemm_f2(
    const int8_t* __restrict__ A, const float* __restrict__ WT,
    const float* __restrict__ bias,
    float* __restrict__ X, int8_t* __restrict__ S,
    int WLD, int XLD, int NTOT) {

    constexpr int KT = KBASE / 32;
    constexpr uint32_t ABUF = 32 * 128 * 4;
    constexpr uint32_t WBUF = 32 * 128 * 4;

    extern __shared__ char smraw[];
    const uint32_t ab0 = smem_u32(smraw);
    const uint32_t wb0 = ab0 + 2 * ABUF;

    const int tid  = threadIdx.x;
    const int trow = tid >> 4;     // 0..15
    const int tcol = tid & 15;     // 0..15
    const int bm0 = blockIdx.y * 128;
    const int bn0 = blockIdx.x * 128;

    const int arowi = tid & 127;
    const int khalf = tid >> 7;    // 0/1
    const int8_t* arow = A + (size_t)(bm0 + arowi) * KBASE + khalf * 16;

    uint4 arg;
    auto ldgA = [&](int t) { arg = *(const uint4*)(arow + t * 32); };
    auto cpW = [&](int t) {
        const float* src = WT + (size_t)(t * 32) * WLD + bn0;
        const uint32_t dst = wb0 + (uint32_t)(t & 1) * WBUF;
#pragma unroll
        for (int q = 0; q < 4; q++) {
            int ch = tid + q * 256;           // 0..1023
            int row = ch >> 5, c16 = ch & 31; // 32 rows x 32 16B-chunks
            cp_async16(dst + (uint32_t)(row * 128 + c16 * 4) * 4,
                       src + (size_t)row * WLD + c16 * 4);
        }
        CP_COMMIT();
    };
    auto stsA = [&](int t) {
        uint32_t base = ab0 + (uint32_t)(t & 1) * ABUF
                      + (uint32_t)(khalf * 16 * 128 + arowi) * 4u;
#pragma unroll
        for (int w = 0; w < 4; w++) {
            uint32_t x = ((const uint32_t*)&arg)[w];
#pragma unroll
            for (int b = 0; b < 4; b++)
                sts32(base + (uint32_t)((w * 4 + b) * 128) * 4u,
                      ((x >> (8 * b)) & 1u) * 0x3f800000u);
        }
    };

    unsigned long long acc[8][4];
#pragma unroll
    for (int i = 0; i < 8; i++)
#pragma unroll
        for (int j = 0; j < 4; j++) acc[i][j] = 0ull;

    // prologue
    ldgA(0); cpW(0); stsA(0);

    for (int i = 0; i < KT; i++) {
        CP_WAIT0();
        __syncthreads();
        if (i + 1 < KT) { cpW(i + 1); ldgA(i + 1); }

        const uint32_t ab = ab0 + (uint32_t)(i & 1) * ABUF + (uint32_t)(trow * 8) * 4u;
        const uint32_t wb = wb0 + (uint32_t)(i & 1) * WBUF + (uint32_t)(tcol * 8) * 4u;
#pragma unroll
        for (int k = 0; k < 32; k++) {
            float4 av0, av1;
            lds_f4(av0, ab + (uint32_t)(k * 128) * 4u);
            lds_f4(av1, ab + (uint32_t)(k * 128) * 4u + 16u);
            unsigned long long ww[4];
            lds_v2u64(ww[0], ww[1], wb + (uint32_t)(k * 128) * 4u);
            lds_v2u64(ww[2], ww[3], wb + (uint32_t)(k * 128) * 4u + 16u);
            unsigned long long aa[8];
            aa[0] = dup2(av0.x); aa[1] = dup2(av0.y); aa[2] = dup2(av0.z); aa[3] = dup2(av0.w);
            aa[4] = dup2(av1.x); aa[5] = dup2(av1.y); aa[6] = dup2(av1.z); aa[7] = dup2(av1.w);
#pragma unroll
            for (int ii = 0; ii < 8; ii++)
#pragma unroll
                for (int jj = 0; jj < 4; jj++) fma2(acc[ii][jj], aa[ii], ww[jj]);
        }
        if (i + 1 < KT) stsA(i + 1);
    }

    if (MODE == 1) {
        // fused hidden-neuron scan over t (thread rows = t 0..7 of batch b)
        float bj[8];
#pragma unroll
        for (int cc = 0; cc < 8; cc++) bj[cc] = bias[bn0 + tcol * 8 + cc];
        unsigned long long srow[8];
#pragma unroll
        for (int i = 0; i < 8; i++) srow[i] = 0ull;
#pragma unroll
        for (int j = 0; j < 4; j++) {
#pragma unroll
            for (int e = 0; e < 2; e++) {
                const int cc = 2 * j + e;
                float c = 0.0f, vv = 0.0f, rr = 0.0f, ss = 0.0f;
#pragma unroll
                for (int i = 0; i < 8; i++) {
                    float xv = e ? f2hi(acc[i][j]) : f2lo(acc[i][j]);
                    c  = c * CDECAY + xv + bj[cc];
                    vv = vv * (1.0f - ss) + ss * THR;
                    rr = rr + ss * THS;
                    float vd = vv * vv - vv - rr + c;
                    float rd = THV * vv - THU * rr;
                    vv += vd; rr += rd;
                    ss = vv > VTH ? 1.0f : 0.0f;
                    srow[i] |= (unsigned long long)(ss != 0.0f ? 1u : 0u) << (8 * cc);
                }
            }
        }
#pragma unroll
        for (int i = 0; i < 8; i++) {
            size_t row = (size_t)(bm0 + trow * 8 + i);
            *(unsigned long long*)&S[row * H_ + bn0 + tcol * 8] = srow[i];
        }
    } else {
#pragma unroll
        for (int i = 0; i < 8; i++) {
            int row = bm0 + trow * 8 + i;
#pragma unroll
            for (int j = 0; j < 4; j++) {
                int col = bn0 + tcol * 8 + 2 * j;
                if (col < NTOT) {
                    *(float2*)&X[(size_t)row * XLD + col] =
                        make_float2(f2lo(acc[i][j]), f2hi(acc[i][j]));
                }
            }
        }
    }
}

// ---------------- weight transpose: w[N][K] -> wt[K][NP], zero-pad n>=N ----------------
__global__ void transpose_w(const float* __restrict__ w, float* __restrict__ wt,
                            int N, int K, int NP) {
    __shared__ float t[32][33];
    int tx = threadIdx.x, ty = threadIdx.y;  // 32 x 8
    int bx = blockIdx.x, by = blockIdx.y;
#pragma unroll
    for (int j = 0; j < 4; j++) {
        int n = bx * 32 + ty + j * 8;
        int k = by * 32 + tx;
        t[ty + j * 8][tx] = (n < N) ? w[(size_t)n * K + k] : 0.0f;
    }
    __syncthreads();
#pragma unroll
    for (int j = 0; j < 4; j++) {
        int k = by * 32 + ty + j * 8;
        int n = bx * 32 + tx;
        wt[(size_t)k * NP + n] = t[tx][ty + j * 8];
    }
}

// ---------------- encoder (writes spikes in m = b*8+t order) ----------------
__global__ void encoder_kernel(const float* __restrict__ obs,
                               const float* __restrict__ mean,
                               const float* __restrict__ stdv) {
    int idx = blockIdx.x * blockDim.x + threadIdx.x;
    if (idx >= B_ * IN_) return;
    int b = idx / IN_;
    int i = idx - b * IN_;
    int o = i / EP_;
    float d  = obs[b * OBS_ + o] - mean[i];
    float sd = stdv[i];
    float a  = expf(-0.5f * d * d / (sd * sd));
    float volt = 0.0f;
    int8_t* sp = g_spikes + (size_t)b * T_ * IN_ + i;
#pragma unroll
    for (int t = 0; t < T_; t++) {
        volt += a;
        float s = volt > 1.0f ? 1.0f : 0.0f;
        volt -= s;
        sp[(size_t)t * IN_] = (int8_t)s;
    }
}

// ---------------- output-layer scan: lateral conv + neuron + fr + decode ----------------
__global__ __launch_bounds__(256) void scan_out(
    const float* __restrict__ x3, const float* __restrict__ b_out,
    const float* __restrict__ conn_w, const float* __restrict__ conn_b,
    const float* __restrict__ dec_w, const float* __restrict__ dec_b,
    float* __restrict__ out) {
    __shared__ float cw[AD_ * DP_ * DP_];   // 1600
    for (int i = threadIdx.x; i < AD_ * DP_ * DP_; i += blockDim.x) cw[i] = conn_w[i];
    __syncthreads();

    int idx = blockIdx.x * blockDim.x + threadIdx.x;   // (b, a)
    if (idx >= B_ * AD_) return;
    int b = idx >> 4;
    int a = idx & 15;

    float cb[DP_], bo[DP_];
#pragma unroll
    for (int j = 0; j < DP_; j++) {
        cb[j] = conn_b[a * DP_ + j];
        bo[j] = b_out[a * DP_ + j];
    }
    const float* cwa = cw + a * DP_ * DP_;

    float cur[DP_], vv[DP_], rr[DP_], sp[DP_], fr[DP_];
#pragma unroll
    for (int j = 0; j < DP_; j++) { cur[j] = 0.f; vv[j] = 0.f; rr[j] = 0.f; sp[j] = 0.f; fr[j] = 0.f; }

    for (int t = 0; t < T_; t++) {
        const float* xp = x3 + ((size_t)b * T_ + t) * OUT_ + a * DP_;
        float sn[DP_];
#pragma unroll
        for (int j = 0; j < DP_; j++) {
            float lat = cb[j];
#pragma unroll
            for (int k = 0; k < DP_; k++) lat += sp[k] * cwa[j * DP_ + k];
            float c  = cur[j] * CDECAY + xp[j] + bo[j] + lat;
            float v2 = vv[j] * (1.0f - sp[j]) + sp[j] * THR;
            float r2 = rr[j] + sp[j] * THS;
            float vd = v2 * v2 - v2 - r2 + c;
            float rd = THV * v2 - THU * r2;
            v2 += vd; r2 += rd;
            sn[j] = v2 > VTH ? 1.0f : 0.0f;
            cur[j] = c; vv[j] = v2; rr[j] = r2;
        }
#pragma unroll
        for (int j = 0; j < DP_; j++) { sp[j] = sn[j]; fr[j] += sn[j]; }
    }

    float raw = dec_b[a];
#pragma unroll
    for (int p = 0; p < DP_; p++) raw += (fr[p] * 0.125f) * dec_w[a * DP_ + p];
    out[idx] = tanhf(raw);
}

// ---------------- launch ----------------
extern "C" void kernel_launch(void* const* d_in, const int* in_sizes, int n_in,
                              void* d_out, int out_size) {
    const float* obs    = (const float*)d_in[0];
    const float* mean   = (const float*)d_in[1];
    const float* stdv   = (const float*)d_in[2];
    const float* w1     = (const float*)d_in[3];
    const float* b1     = (const float*)d_in[4];
    const float* w2     = (const float*)d_in[5];
    const float* b2     = (const float*)d_in[6];
    const float* w_out  = (const float*)d_in[7];
    const float* b_out  = (const float*)d_in[8];
    const float* conn_w = (const float*)d_in[9];
    const float* conn_b = (const float*)d_in[10];
    const float* dec_w  = (const float*)d_in[11];
    const float* dec_b  = (const float*)d_in[12];
    float* out = (float*)d_out;

    int8_t *spikes, *sa, *sb;
    float *x3, *w1t, *w2t, *wot;
    cudaGetSymbolAddress((void**)&spikes, g_spikes);
    cudaGetSymbolAddress((void**)&sa,  g_sa);
    cudaGetSymbolAddress((void**)&sb,  g_sb);
    cudaGetSymbolAddress((void**)&x3,  g_x3);
    cudaGetSymbolAddress((void**)&w1t, g_w1t);
    cudaGetSymbolAddress((void**)&w2t, g_w2t);
    cudaGetSymbolAddress((void**)&wot, g_wot);

    const int smemG = 2 * 32 * 128 * 4 + 2 * 32 * 128 * 4;  // 65536
    cudaFuncSetAttribute(gemm_f2<640, 1>,  cudaFuncAttributeMaxDynamicSharedMemorySize, smemG);
    cudaFuncSetAttribute(gemm_f2<1024, 1>, cudaFuncAttributeMaxDynamicSharedMemorySize, smemG);
    cudaFuncSetAttribute(gemm_f2<1024, 0>, cudaFuncAttributeMaxDynamicSharedMemorySize, smemG);

    {
        dim3 tb(32, 8);
        transpose_w<<<dim3(32, 20), tb>>>(w1, w1t, H_, IN_, H_);
        transpose_w<<<dim3(32, 32), tb>>>(w2, w2t, H_, H_, H_);
        transpose_w<<<dim3(8, 32),  tb>>>(w_out, wot, OUT_, H_, 256);
    }
    encoder_kernel<<<(B_ * IN_ + 255) / 256, 256>>>(obs, mean, stdv);

    // L1: s1 = scan(spikes_all @ W1)   (M=32768, K=640, N=1024, fused scan)
    gemm_f2<640, 1><<<dim3(8, M_ / 128), 256, smemG>>>(
        spikes, w1t, b1, nullptr, sa, H_, H_, H_);

    // L2: s2 = scan(s1_all @ W2)       (M=32768, K=1024, N=1024, fused scan)
    gemm_f2<1024, 1><<<dim3(8, M_ / 128), 256, smemG>>>(
        sa, w2t, b2, nullptr, sb, H_, H_, H_);

    // L3: X3 = s2_all @ Wout           (M=32768, K=1024, N=160 padded 256)
    gemm_f2<1024, 0><<<dim3(2, M_ / 128), 256, smemG>>>(
        sb, wot, nullptr, x3, nullptr, 256, OUT_, OUT_);

    // output scan: lateral + neuron + fr + decode
    scan_out<<<(B_ * AD_ + 255) / 256, 256>>>(x3, b_out, conn_w, conn_b, dec_w, dec_b, out);
}